// round 5
// baseline (speedup 1.0000x reference)
#include <cuda_runtime.h>
#include <cuda_fp16.h>
#include <stdint.h>

#define NR  65536
#define KC  8192
#define DIM 256
#define ND  (NR*DIM)
#define CAP 64
#define MARGIN 6e-5f

#define BM  256                 // rows per CTA
#define NCH 128                 // 8192/64 chunks of 64 codes

__device__ float  g_znorm[NR];
__device__ int    g_idx[NR];
__device__ double g_part[NR];
__device__ double g_part2[128];
__device__ int    g_cnt[NR];
__device__ int    g_cand[(size_t)NR*CAP];
__device__ float  g_candd[(size_t)NR*CAP];
__device__ __align__(128) __half g_zh[ND];
__device__ __align__(128) __half g_wh[KC*DIM];

__device__ __forceinline__ uint32_t smem_u32(const void* p) {
    uint32_t a;
    asm("{ .reg .u64 t; cvta.to.shared.u64 t, %1; cvt.u32.u64 %0, t; }" : "=r"(a) : "l"(p));
    return a;
}
__device__ __forceinline__ void cp16(uint32_t dst, const void* src) {
    asm volatile("cp.async.cg.shared.global [%0], [%1], 16;" :: "r"(dst), "l"(src) : "memory");
}
#define CPC()  asm volatile("cp.async.commit_group;" ::: "memory")
#define CPW0() asm volatile("cp.async.wait_group 0;" ::: "memory")
#define CPW1() asm volatile("cp.async.wait_group 1;" ::: "memory")
#define LDSM4(r0,r1,r2,r3,a) \
    asm volatile("ldmatrix.sync.aligned.m8n8.x4.shared.b16 {%0,%1,%2,%3}, [%4];" \
        : "=r"(r0),"=r"(r1),"=r"(r2),"=r"(r3) : "r"(a))
#define MMA(d,a0,a1,a2,a3,b0,b1) \
    asm volatile("mma.sync.aligned.m16n8k16.row.col.f32.f16.f16.f32 " \
        "{%0,%1,%2,%3}, {%4,%5,%6,%7}, {%8,%9}, {%0,%1,%2,%3};" \
        : "+f"(d[0]),"+f"(d[1]),"+f"(d[2]),"+f"(d[3]) \
        : "r"(a0),"r"(a1),"r"(a2),"r"(a3),"r"(b0),"r"(b1))

// ---- per-row ||z||^2 (validated order) + z->fp16 + zero capture counters ----
__global__ void znorm_kernel(const float* __restrict__ z) {
    int warp = threadIdx.x >> 5, lane = threadIdx.x & 31;
    int row  = blockIdx.x * 8 + warp;
    const float* zr = z + (size_t)row * DIM;
    float s = 0.0f;
    #pragma unroll
    for (int t = 0; t < 8; t++) {
        float v = zr[t * 32 + lane];
        g_zh[(size_t)row * DIM + t * 32 + lane] = __float2half(v);
        s = __fadd_rn(s, __fmul_rn(v, v));
    }
    #pragma unroll
    for (int off = 16; off > 0; off >>= 1)
        s = __fadd_rn(s, __shfl_xor_sync(0xffffffffu, s, off));
    if (lane == 0) { g_znorm[row] = s; g_cnt[row] = 0; }
}
// ---- W -> fp16 scaled by 2^13 (exact) ----
__global__ void wconv_kernel(const float* __restrict__ W) {
    int i = blockIdx.x * 256 + threadIdx.x;
    g_wh[i] = __float2half(W[i] * 8192.0f);
}

// ---- Phase 1: HMMA approx distances + candidate capture, BM=256 rows/CTA ----
// 8 warps, each owns 32 rows x all 64 chunk cols. smem: A 256x512B @0,
// B 2x(64x512B) @131072. Swizzle (validated): off(r,c16)=r*512+((c16^(r&7))<<4)
__global__ __launch_bounds__(256, 1) void phase1_kernel() {
    extern __shared__ __align__(128) char sm[];
    const int tid = threadIdx.x, lane = tid & 31, wid = tid >> 5;
    const int rowbase = blockIdx.x * BM;
    const uint32_t sb = smem_u32(sm);

    // stage A (256 rows of z_h) + B chunk 0  -> group0
    for (int i = tid; i < BM * 32; i += 256) {
        int r = i >> 5, c = i & 31;
        cp16(sb + r*512 + ((c ^ (r&7)) << 4), g_zh + (size_t)(rowbase+r)*DIM + c*8);
    }
    for (int i = tid; i < 2048; i += 256) {
        int r = i >> 5, c = i & 31;
        cp16(sb + 131072 + r*512 + ((c ^ (r&7)) << 4), g_wh + (size_t)r*DIM + c*8);
    }
    CPC();
    // B chunk 1 -> group1
    for (int i = tid; i < 2048; i += 256) {
        int r = i >> 5, c = i & 31;
        cp16(sb + 163840 + r*512 + ((c ^ (r&7)) << 4), g_wh + (size_t)(64 + r)*DIM + c*8);
    }
    CPC();
    CPW1(); __syncthreads();          // A + B0 ready; B1 in flight

    const int wm = wid * 32;
    const int q  = lane & 7;                          // swizzle XOR (all paths)
    const int ac1 = lane >> 4;
    const int bc1 = (lane >> 3) & 1;
    const int brl = (lane & 7) + ((lane & 16) >> 1);
    const uint32_t aB0 = sb + (wm + (lane & 15)) * 512;
    const uint32_t aB1 = aB0 + 16 * 512;

    float zn[4];
    #pragma unroll
    for (int h = 0; h < 4; h++)
        zn[h] = g_znorm[rowbase + wm + (h >> 1) * 16 + (h & 1) * 8 + (lane >> 2)];
    float rm[4] = {3.4e38f, 3.4e38f, 3.4e38f, 3.4e38f};

    for (int ch = 0; ch < NCH; ch++) {
        const uint32_t bB = sb + 131072 + (ch & 1) * 32768;
        float acc[2][8][4];
        #pragma unroll
        for (int mt = 0; mt < 2; mt++)
            #pragma unroll
            for (int nb = 0; nb < 8; nb++)
                #pragma unroll
                for (int p = 0; p < 4; p++) acc[mt][nb][p] = 0.0f;

        const uint32_t bR0 = bB + brl * 512;

        #pragma unroll
        for (int k = 0; k < 16; k++) {
            const uint32_t aoff = (uint32_t)(((2*k + ac1) ^ q) << 4);
            const uint32_t boff = (uint32_t)(((2*k + bc1) ^ q) << 4);
            uint32_t a0,a1,a2,a3, a4,a5,a6,a7;
            LDSM4(a0,a1,a2,a3, aB0 + aoff);
            LDSM4(a4,a5,a6,a7, aB1 + aoff);
            #pragma unroll
            for (int g = 0; g < 4; g++) {
                uint32_t b0,b1,b2,b3;
                LDSM4(b0,b1,b2,b3, bR0 + g * (16*512) + boff);
                MMA(acc[0][2*g],   a0,a1,a2,a3, b0,b1);
                MMA(acc[0][2*g+1], a0,a1,a2,a3, b2,b3);
                MMA(acc[1][2*g],   a4,a5,a6,a7, b0,b1);
                MMA(acc[1][2*g+1], a4,a5,a6,a7, b2,b3);
            }
        }

        // epilogue: dist = fl(zn - acc*2^-12); capture within margin of run-min
        const int colb = ch * 64 + 2 * (lane & 3);
        #pragma unroll
        for (int mt = 0; mt < 2; mt++) {
            #pragma unroll
            for (int nb = 0; nb < 8; nb++) {
                #pragma unroll
                for (int p = 0; p < 4; p++) {
                    const int h = mt * 2 + (p >> 1);
                    float d = __fmaf_rn(acc[mt][nb][p], -2.44140625e-4f, zn[h]);
                    if (d < rm[h] + MARGIN) {
                        int row = rowbase + wm + mt*16 + (p >> 1)*8 + (lane >> 2);
                        int pos = atomicAdd(&g_cnt[row], 1);
                        if (pos < CAP) {
                            g_cand [(size_t)row*CAP + pos] = colb + nb*8 + (p & 1);
                            g_candd[(size_t)row*CAP + pos] = d;
                        }
                        if (d < rm[h]) rm[h] = d;
                    }
                }
            }
        }
        #pragma unroll
        for (int h = 0; h < 4; h++) {
            rm[h] = fminf(rm[h], __shfl_xor_sync(0xffffffffu, rm[h], 1));
            rm[h] = fminf(rm[h], __shfl_xor_sync(0xffffffffu, rm[h], 2));
        }

        __syncthreads();                       // all warps done reading buf ch&1
        if (ch + 2 < NCH) {                    // refill it for chunk ch+2
            const __half* src = g_wh + (size_t)(ch + 2) * 64 * DIM;
            const uint32_t nb_ = sb + 131072 + (ch & 1) * 32768;
            for (int i = tid; i < 2048; i += 256) {
                int r = i >> 5, c = i & 31;
                cp16(nb_ + r*512 + ((c ^ (r&7)) << 4), src + (size_t)r*DIM + c*8);
            }
            CPC(); CPW1();
        } else {
            CPW0();
        }
        __syncthreads();                       // chunk ch+1 visible to all
    }
}

// ---- Phase 2: exact fp32 rescore (validated) ----
__global__ void phase2_kernel(const float* __restrict__ z, const float* __restrict__ W) {
    const int wid = threadIdx.x >> 5, lane = threadIdx.x & 31;
    const int row = blockIdx.x * 8 + wid;
    const int cnt = g_cnt[row];
    const float zn = g_znorm[row];
    const float* zr = z + (size_t)row * DIM;
    unsigned long long best = 0xFFFFFFFFFFFFFFFFull;

    if (cnt <= CAP) {
        float rmin = 3.4e38f;
        for (int i = lane; i < cnt; i += 32)
            rmin = fminf(rmin, g_candd[(size_t)row*CAP + i]);
        #pragma unroll
        for (int o = 16; o > 0; o >>= 1)
            rmin = fminf(rmin, __shfl_xor_sync(0xffffffffu, rmin, o));
        for (int i = lane; i < cnt; i += 32) {
            float d = g_candd[(size_t)row*CAP + i];
            if (d <= rmin + MARGIN) {
                int idx = g_cand[(size_t)row*CAP + i];
                const float* wr = W + (size_t)idx * DIM;
                float acc = 0.0f;
                #pragma unroll 8
                for (int k = 0; k < DIM; k++) acc = __fmaf_rn(zr[k], wr[k], acc);
                float dist = __fadd_rn(zn, __fmul_rn(-2.0f, acc));
                unsigned long long key =
                    ((unsigned long long)__float_as_uint(dist) << 32) | (unsigned)idx;
                if (key < best) best = key;
            }
        }
    } else {
        for (int c = lane; c < KC; c += 32) {
            const float* wr = W + (size_t)c * DIM;
            float acc = 0.0f;
            #pragma unroll 8
            for (int k = 0; k < DIM; k++) acc = __fmaf_rn(zr[k], wr[k], acc);
            float dist = __fadd_rn(zn, __fmul_rn(-2.0f, acc));
            unsigned long long key =
                ((unsigned long long)__float_as_uint(dist) << 32) | (unsigned)c;
            if (key < best) best = key;
        }
    }
    #pragma unroll
    for (int o = 16; o > 0; o >>= 1) {
        unsigned long long ot = __shfl_xor_sync(0xffffffffu, best, o);
        if (ot < best) best = ot;
    }
    if (lane == 0) g_idx[row] = (int)(best & 0xffffffffu);
}

// ---- output + loss (validated) ----
__global__ void output_kernel(const float* __restrict__ z, const float* __restrict__ W,
                              float* __restrict__ out, int out_size) {
    int row = blockIdx.x, d = threadIdx.x;
    int idx = g_idx[row];
    float zv = z[(size_t)row * DIM + d];
    float wv = W[(size_t)idx * DIM + d];
    float dq  = __fadd_rn(wv, -zv);
    float qst = __fadd_rn(zv, dq);
    if (out_size >= ND) out[(size_t)row * DIM + d] = qst;
    float sq = __fmul_rn(dq, dq);
    __shared__ double sd[DIM];
    sd[d] = (double)sq;
    __syncthreads();
    #pragma unroll
    for (int off = DIM / 2; off > 0; off >>= 1) {
        if (d < off) sd[d] += sd[d + off];
        __syncthreads();
    }
    if (d == 0) {
        g_part[row] = sd[0];
        if (out_size >= ND + 1 + NR) out[ND + 1 + row] = (float)idx;
    }
}
__global__ void finalize1_kernel() {
    __shared__ double sd[256];
    int t = threadIdx.x, b = blockIdx.x;
    sd[t] = g_part[b*512 + t] + g_part[b*512 + 256 + t];
    __syncthreads();
    #pragma unroll
    for (int off = 128; off > 0; off >>= 1) {
        if (t < off) sd[t] += sd[t + off];
        __syncthreads();
    }
    if (t == 0) g_part2[b] = sd[0];
}
__global__ void finalize2_kernel(float* __restrict__ out, int out_size) {
    __shared__ double sd[128];
    int t = threadIdx.x;
    sd[t] = g_part2[t];
    __syncthreads();
    #pragma unroll
    for (int off = 64; off > 0; off >>= 1) {
        if (t < off) sd[t] += sd[t + off];
        __syncthreads();
    }
    if (t == 0 && out_size >= ND + 1) {
        float m = (float)(sd[0] / (double)ND);
        out[ND] = __fadd_rn(m, __fmul_rn(0.25f, m));
    }
}

extern "C" void kernel_launch(void* const* d_in, const int* in_sizes, int n_in,
                              void* d_out, int out_size) {
    const float *z, *W;
    if (in_sizes[0] == NR * DIM) { z = (const float*)d_in[0]; W = (const float*)d_in[1]; }
    else                         { z = (const float*)d_in[1]; W = (const float*)d_in[0]; }
    float* out = (float*)d_out;

    znorm_kernel<<<NR / 8, 256>>>(z);
    wconv_kernel<<<KC * DIM / 256, 256>>>(W);

    static int done = 0;
    if (!done) {
        cudaFuncSetAttribute(phase1_kernel, cudaFuncAttributeMaxDynamicSharedMemorySize,
                             196608);
        done = 1;
    }
    phase1_kernel<<<NR / BM, 256, 196608>>>();
    phase2_kernel<<<NR / 8, 256>>>(z, W);

    output_kernel<<<NR, DIM>>>(z, W, out, out_size);
    finalize1_kernel<<<128, 256>>>();
    finalize2_kernel<<<1, 128>>>(out, out_size);
}